// round 1
// baseline (speedup 1.0000x reference)
#include <cuda_runtime.h>
#include <math.h>

#define B_ROWS 16384
#define K_DIM  1024
#define H_DIM  1024
#define FH     4096
#define EPS    1e-5f

// Scratch for the two GEMM outputs: [2][B_ROWS][FH] fp32 = 512 MB.
__device__ float g_scratch[134217728];

// ---------------------------------------------------------------------------
// GEMM (NT): C[m,n] = sum_k A[m,k] * W[n,k]
// A: [M, K] row-major, W: [N, K] row-major. blockIdx.z selects (x,W_i2h) vs (h,W_h2h).
// Tile: BM=128, BN=128, BK=16, 256 threads, 8x8 per thread.
// ---------------------------------------------------------------------------
#define BM 128
#define BN 128
#define BK 16

__global__ void __launch_bounds__(256, 2) gemm_nt_kernel(
    const float* __restrict__ A0, const float* __restrict__ A1,
    const float* __restrict__ W0, const float* __restrict__ W1)
{
    const int M = B_ROWS, N = FH, K = K_DIM;
    const float* A = blockIdx.z ? A1 : A0;
    const float* W = blockIdx.z ? W1 : W0;
    float* C = g_scratch + (size_t)blockIdx.z * (size_t)M * (size_t)N;

    __shared__ float As[BK][BM];
    __shared__ float Bs[BK][BN];

    const int tid = threadIdx.x;
    const int m0 = blockIdx.y * BM;
    const int n0 = blockIdx.x * BN;
    const int tx = tid & 15;   // n direction (16)
    const int ty = tid >> 4;   // m direction (16)

    const int lrow = tid >> 2;        // 0..63
    const int lcol = (tid & 3) << 2;  // 0,4,8,12

    const float* Aptr = A + (size_t)(m0 + lrow) * K + lcol;
    const float* Wptr = W + (size_t)(n0 + lrow) * K + lcol;

    float acc[8][8];
    #pragma unroll
    for (int i = 0; i < 8; i++)
        #pragma unroll
        for (int j = 0; j < 8; j++) acc[i][j] = 0.f;

    for (int k0 = 0; k0 < K; k0 += BK) {
        #pragma unroll
        for (int r = 0; r < 2; ++r) {
            float4 va = *(const float4*)(Aptr + (size_t)r * 64 * K + k0);
            As[lcol + 0][lrow + r * 64] = va.x;
            As[lcol + 1][lrow + r * 64] = va.y;
            As[lcol + 2][lrow + r * 64] = va.z;
            As[lcol + 3][lrow + r * 64] = va.w;
            float4 vb = *(const float4*)(Wptr + (size_t)r * 64 * K + k0);
            Bs[lcol + 0][lrow + r * 64] = vb.x;
            Bs[lcol + 1][lrow + r * 64] = vb.y;
            Bs[lcol + 2][lrow + r * 64] = vb.z;
            Bs[lcol + 3][lrow + r * 64] = vb.w;
        }
        __syncthreads();

        #pragma unroll
        for (int kk = 0; kk < BK; ++kk) {
            float a[8], b[8];
            #pragma unroll
            for (int i = 0; i < 8; i++) a[i] = As[kk][ty * 8 + i];
            #pragma unroll
            for (int j = 0; j < 8; j++) b[j] = Bs[kk][tx * 8 + j];
            #pragma unroll
            for (int i = 0; i < 8; i++)
                #pragma unroll
                for (int j = 0; j < 8; j++)
                    acc[i][j] = fmaf(a[i], b[j], acc[i][j]);
        }
        __syncthreads();
    }

    #pragma unroll
    for (int i = 0; i < 8; i++) {
        float* Crow = C + (size_t)(m0 + ty * 8 + i) * N + n0 + tx * 8;
        #pragma unroll
        for (int j = 0; j < 8; j += 4) {
            float4 v = make_float4(acc[i][j], acc[i][j + 1], acc[i][j + 2], acc[i][j + 3]);
            *(float4*)(Crow + j) = v;
        }
    }
}

// ---------------------------------------------------------------------------
// Fused epilogue: per row b —
//   LN(i2h_row) + LN(h2h_row) + bias -> gates f,i,o,g
//   c_new = sig(f)*c + sig(i)*tanh(g)
//   h_new = sig(o)*tanh(LN(c_new))
// One block (256 threads) per row. Both 4096-rows cached in smem.
// Output layout: [h_new (B*H)] then [c_new (B*H)].
// ---------------------------------------------------------------------------
__device__ __forceinline__ float block_reduce(float v, float* red) {
    const int tid = threadIdx.x;
    #pragma unroll
    for (int o = 16; o > 0; o >>= 1) v += __shfl_xor_sync(0xffffffffu, v, o);
    __syncthreads();   // protect red across consecutive calls
    if ((tid & 31) == 0) red[tid >> 5] = v;
    __syncthreads();
    float r = red[0];
    #pragma unroll
    for (int w = 1; w < 8; w++) r += red[w];
    return r;
}

__device__ __forceinline__ float sigf(float x) { return 1.f / (1.f + expf(-x)); }

__global__ void __launch_bounds__(256, 1) epilogue_kernel(
    const float* __restrict__ c,
    const float* __restrict__ gi, const float* __restrict__ bi,
    const float* __restrict__ gh, const float* __restrict__ bh,
    const float* __restrict__ gc, const float* __restrict__ bc,
    const float* __restrict__ bias,
    float* __restrict__ out)
{
    __shared__ float si[FH];
    __shared__ float sh[FH];
    __shared__ float red[8];

    const int row = blockIdx.x;
    const int tid = threadIdx.x;

    const float4* pi = (const float4*)(g_scratch + (size_t)row * FH);
    const float4* ph = (const float4*)(g_scratch + (size_t)B_ROWS * FH + (size_t)row * FH);

    float s1 = 0.f, s2 = 0.f, t1 = 0.f, t2 = 0.f;
    #pragma unroll
    for (int idx = tid; idx < FH / 4; idx += 256) {
        float4 v = pi[idx];
        ((float4*)si)[idx] = v;
        s1 += v.x + v.y + v.z + v.w;
        s2 += v.x * v.x + v.y * v.y + v.z * v.z + v.w * v.w;
        float4 w = ph[idx];
        ((float4*)sh)[idx] = w;
        t1 += w.x + w.y + w.z + w.w;
        t2 += w.x * w.x + w.y * w.y + w.z * w.z + w.w * w.w;
    }
    float S1 = block_reduce(s1, red);
    float S2 = block_reduce(s2, red);
    float T1 = block_reduce(t1, red);
    float T2 = block_reduce(t2, red);

    const float inv = 1.f / (float)FH;
    const float mu_i = S1 * inv;
    const float mu_h = T1 * inv;
    const float rs_i = rsqrtf(S2 * inv - mu_i * mu_i + EPS);
    const float rs_h = rsqrtf(T2 * inv - mu_h * mu_h + EPS);

    float cn[4], lo_[4];
    float cs1 = 0.f, cs2 = 0.f;
    #pragma unroll
    for (int kq = 0; kq < 4; kq++) {
        const int j = tid + kq * 256;
        const int jf = j, ji = j + 1024, jo = j + 2048, jg = j + 3072;
        float lf = (si[jf] - mu_i) * rs_i * gi[jf] + bi[jf]
                 + (sh[jf] - mu_h) * rs_h * gh[jf] + bh[jf] + bias[jf];
        float li = (si[ji] - mu_i) * rs_i * gi[ji] + bi[ji]
                 + (sh[ji] - mu_h) * rs_h * gh[ji] + bh[ji] + bias[ji];
        float lo = (si[jo] - mu_i) * rs_i * gi[jo] + bi[jo]
                 + (sh[jo] - mu_h) * rs_h * gh[jo] + bh[jo] + bias[jo];
        float lg = (si[jg] - mu_i) * rs_i * gi[jg] + bi[jg]
                 + (sh[jg] - mu_h) * rs_h * gh[jg] + bh[jg] + bias[jg];
        float cv = sigf(lf) * c[(size_t)row * H_DIM + j] + sigf(li) * tanhf(lg);
        cn[kq] = cv;
        lo_[kq] = lo;
        cs1 += cv;
        cs2 += cv * cv;
    }
    float C1 = block_reduce(cs1, red);
    float C2 = block_reduce(cs2, red);
    const float invH = 1.f / (float)H_DIM;
    const float mu_c = C1 * invH;
    const float rs_c = rsqrtf(C2 * invH - mu_c * mu_c + EPS);

    float* out_h = out;
    float* out_c = out + (size_t)B_ROWS * H_DIM;
    #pragma unroll
    for (int kq = 0; kq < 4; kq++) {
        const int j = tid + kq * 256;
        float cl = (cn[kq] - mu_c) * rs_c * gc[j] + bc[j];
        out_h[(size_t)row * H_DIM + j] = sigf(lo_[kq]) * tanhf(cl);
        out_c[(size_t)row * H_DIM + j] = cn[kq];
    }
}

// ---------------------------------------------------------------------------
extern "C" void kernel_launch(void* const* d_in, const int* in_sizes, int n_in,
                              void* d_out, int out_size) {
    const float* x    = (const float*)d_in[0];
    const float* h    = (const float*)d_in[1];
    const float* c    = (const float*)d_in[2];
    const float* Wi   = (const float*)d_in[3];
    const float* Wh   = (const float*)d_in[4];
    const float* gi   = (const float*)d_in[5];
    const float* bi   = (const float*)d_in[6];
    const float* gh   = (const float*)d_in[7];
    const float* bh   = (const float*)d_in[8];
    const float* gc   = (const float*)d_in[9];
    const float* bc   = (const float*)d_in[10];
    const float* bias = (const float*)d_in[11];
    float* out = (float*)d_out;

    dim3 gg(FH / BN, B_ROWS / BM, 2);
    gemm_nt_kernel<<<gg, 256>>>(x, h, Wi, Wh);
    epilogue_kernel<<<B_ROWS, 256>>>(c, gi, bi, gh, bh, gc, bc, bias, out);
}

// round 5
// speedup vs baseline: 3.6572x; 3.6572x over previous
#include <cuda_runtime.h>
#include <cstdint>
#include <math.h>

#define B_ROWS 16384
#define K_DIM  1024
#define H_DIM  1024
#define FH     4096
#define EPS    1e-5f

// Scratch: [i2h logits 64M][h2h logits 64M][xc 16M][hc 16M][Wic 4M][Whc 4M] floats
#define OFF_I2H 0
#define OFF_H2H 67108864ull
#define OFF_XC  134217728ull
#define OFF_HC  150994944ull
#define OFF_WIC 167772160ull
#define OFF_WHC 171966464ull
__device__ float g_scratch[176160768];

__device__ __forceinline__ uint32_t smem_u32(const void* p) {
    uint32_t a;
    asm("{ .reg .u64 t; cvta.to.shared.u64 t, %1; cvt.u32.u64 %0, t; }" : "=r"(a) : "l"(p));
    return a;
}

// ===========================================================================
// tf32 RN conversion pass
// ===========================================================================
__global__ void conv_tf32_kernel(const float4* __restrict__ in, uint4* __restrict__ out, int n4) {
    for (int i = blockIdx.x * blockDim.x + threadIdx.x; i < n4; i += gridDim.x * blockDim.x) {
        float4 v = in[i];
        uint4 o;
        asm("cvt.rna.tf32.f32 %0, %1;" : "=r"(o.x) : "f"(v.x));
        asm("cvt.rna.tf32.f32 %0, %1;" : "=r"(o.y) : "f"(v.y));
        asm("cvt.rna.tf32.f32 %0, %1;" : "=r"(o.z) : "f"(v.z));
        asm("cvt.rna.tf32.f32 %0, %1;" : "=r"(o.w) : "f"(v.w));
        out[i] = o;
    }
}

// ===========================================================================
// tf32 mma.sync GEMM: C[m,n] = sum_k A[m,k]*W[n,k]  (both K-major, NT)
// Tile 128x128x32, 256 threads (8 warps: 4m x 2n, warp tile 32x64),
// 4-stage cp.async pipeline, ldmatrix.x4 fragment loads, reg double-buffer.
// ===========================================================================
#define STAGES 4
#define ITERS  32            // K=1024 / BK=32
#define STAGE_BYTES 32768    // A 16KB + B 16KB
#define ROW_BYTES 128        // 32 floats per row

__device__ __forceinline__ void stage_load(uint32_t abase, uint32_t bbase,
                                           const float* __restrict__ A, const float* __restrict__ W,
                                           int m0, int n0, int kb, int tid) {
    #pragma unroll
    for (int i = 0; i < 4; i++) {
        int c = tid + i * 256;           // 0..1023
        int r = c >> 3, q = c & 7;
        uint32_t sw = (uint32_t)(r * ROW_BYTES + (((q ^ (r & 7))) << 4));
        const float* ga = A + (size_t)(m0 + r) * K_DIM + kb + q * 4;
        const float* gb = W + (size_t)(n0 + r) * K_DIM + kb + q * 4;
        asm volatile("cp.async.cg.shared.global [%0], [%1], 16;" :: "r"(abase + sw), "l"(ga));
        asm volatile("cp.async.cg.shared.global [%0], [%1], 16;" :: "r"(bbase + sw), "l"(gb));
    }
    asm volatile("cp.async.commit_group;" ::: "memory");
}

#define LDSM_X4(r0, r1, r2, r3, a) \
    asm volatile("ldmatrix.sync.aligned.m8n8.x4.shared.b16 {%0,%1,%2,%3}, [%4];" \
        : "=r"(r0), "=r"(r1), "=r"(r2), "=r"(r3) : "r"(a))

#define MMA_TF32(d, a, b) \
    asm volatile("mma.sync.aligned.m16n8k8.row.col.f32.tf32.tf32.f32 " \
        "{%0,%1,%2,%3}, {%4,%5,%6,%7}, {%8,%9}, {%0,%1,%2,%3};" \
        : "+f"((d)[0]), "+f"((d)[1]), "+f"((d)[2]), "+f"((d)[3]) \
        : "r"((a)[0]), "r"((a)[1]), "r"((a)[2]), "r"((a)[3]), "r"((b)[0]), "r"((b)[1]))

__global__ void __launch_bounds__(256, 1) gemm_tc_kernel(
    const float* __restrict__ A0, const float* __restrict__ A1,
    const float* __restrict__ W0, const float* __restrict__ W1)
{
    extern __shared__ __align__(128) char smem[];
    const uint32_t sb = smem_u32(smem);
    const int tid = threadIdx.x, wid = tid >> 5, l = tid & 31;
    const int m0 = blockIdx.y * 128, n0 = blockIdx.x * 128;
    const float* A = blockIdx.z ? A1 : A0;
    const float* W = blockIdx.z ? W1 : W0;
    float* C = g_scratch + (blockIdx.z ? OFF_H2H : OFF_I2H);

    const int mw = (wid & 3) * 32;       // warp m offset
    const int nw = (wid >> 2) * 64;      // warp n offset

    // ldmatrix per-lane addressing precompute
    const int rA0 = mw + ((l >> 3) & 1) * 8 + (l & 7);
    const int cbA = (l >> 4);
    const int rB0 = nw + (l >> 4) * 8 + (l & 7);
    const int cbB = (l >> 3) & 1;

    uint32_t offA[2]; int xA[2];
    #pragma unroll
    for (int mf = 0; mf < 2; mf++) { int r = rA0 + mf * 16; offA[mf] = r * ROW_BYTES; xA[mf] = r & 7; }
    uint32_t offB[4]; int xB[4];
    #pragma unroll
    for (int p = 0; p < 4; p++) { int r = rB0 + p * 16; offB[p] = r * ROW_BYTES; xB[p] = r & 7; }

    float acc[2][8][4];
    #pragma unroll
    for (int mf = 0; mf < 2; mf++)
        #pragma unroll
        for (int nf = 0; nf < 8; nf++)
            #pragma unroll
            for (int e = 0; e < 4; e++) acc[mf][nf][e] = 0.f;

    // prologue: fill STAGES-1 stages
    #pragma unroll
    for (int s = 0; s < STAGES - 1; s++)
        stage_load(sb + s * STAGE_BYTES, sb + s * STAGE_BYTES + 16384, A, W, m0, n0, s * 32, tid);

    uint32_t af[2][2][4];   // [buf][mf][reg]
    uint32_t bf[2][4][4];   // [buf][pair][reg]

    for (int kt = 0; kt < ITERS; kt++) {
        asm volatile("cp.async.wait_group 2;" ::: "memory");
        __syncthreads();
        const uint32_t Ab = sb + (kt & (STAGES - 1)) * STAGE_BYTES;
        const uint32_t Bb = Ab + 16384;

        // load kstep 0 fragments
        #pragma unroll
        for (int mf = 0; mf < 2; mf++) {
            uint32_t a = Ab + offA[mf] + (((cbA) ^ xA[mf]) << 4);
            LDSM_X4(af[0][mf][0], af[0][mf][1], af[0][mf][2], af[0][mf][3], a);
        }
        #pragma unroll
        for (int p = 0; p < 4; p++) {
            uint32_t a = Bb + offB[p] + (((cbB) ^ xB[p]) << 4);
            LDSM_X4(bf[0][p][0], bf[0][p][1], bf[0][p][2], bf[0][p][3], a);
        }

        // prefetch next tile
        if (kt + STAGES - 1 < ITERS) {
            const uint32_t Pb = sb + ((kt + STAGES - 1) & (STAGES - 1)) * STAGE_BYTES;
            stage_load(Pb, Pb + 16384, A, W, m0, n0, (kt + STAGES - 1) * 32, tid);
        } else {
            asm volatile("cp.async.commit_group;" ::: "memory");
        }

        #pragma unroll
        for (int j = 0; j < 4; j++) {
            const int cur = j & 1, nxt = cur ^ 1;
            if (j < 3) {
                const int q = 2 * (j + 1);
                #pragma unroll
                for (int mf = 0; mf < 2; mf++) {
                    uint32_t a = Ab + offA[mf] + (((q + cbA) ^ xA[mf]) << 4);
                    LDSM_X4(af[nxt][mf][0], af[nxt][mf][1], af[nxt][mf][2], af[nxt][mf][3], a);
                }
                #pragma unroll
                for (int p = 0; p < 4; p++) {
                    uint32_t a = Bb + offB[p] + (((q + cbB) ^ xB[p]) << 4);
                    LDSM_X4(bf[nxt][p][0], bf[nxt][p][1], bf[nxt][p][2], bf[nxt][p][3], a);
                }
            }
            #pragma unroll
            for (int mf = 0; mf < 2; mf++)
                #pragma unroll
                for (int nf = 0; nf < 8; nf++) {
                    uint32_t b2[2] = { bf[cur][nf >> 1][(nf & 1) * 2], bf[cur][nf >> 1][(nf & 1) * 2 + 1] };
                    MMA_TF32(acc[mf][nf], af[cur][mf], b2);
                }
        }
    }

    // store accumulators: d0,d1 @ (row g, cols 2c,2c+1); d2,d3 @ row g+8
    const int g = l >> 2, cc = (l & 3) * 2;
    #pragma unroll
    for (int mf = 0; mf < 2; mf++) {
        #pragma unroll
        for (int nf = 0; nf < 8; nf++) {
            const int col = n0 + nw + nf * 8 + cc;
            float* p0 = C + (size_t)(m0 + mw + mf * 16 + g) * FH + col;
            float* p1 = p0 + 8 * FH;
            asm volatile("st.global.v2.f32 [%0], {%1,%2};" :: "l"(p0), "f"(acc[mf][nf][0]), "f"(acc[mf][nf][1]) : "memory");
            asm volatile("st.global.v2.f32 [%0], {%1,%2};" :: "l"(p1), "f"(acc[mf][nf][2]), "f"(acc[mf][nf][3]) : "memory");
        }
    }
}

// ===========================================================================
// Fused LN+LSTM epilogue
// ===========================================================================
__device__ __forceinline__ float block_reduce(float v, float* red) {
    const int tid = threadIdx.x;
    #pragma unroll
    for (int o = 16; o > 0; o >>= 1) v += __shfl_xor_sync(0xffffffffu, v, o);
    __syncthreads();
    if ((tid & 31) == 0) red[tid >> 5] = v;
    __syncthreads();
    float r = red[0];
    #pragma unroll
    for (int w = 1; w < 8; w++) r += red[w];
    return r;
}
__device__ __forceinline__ float sigf(float x) { return 1.f / (1.f + expf(-x)); }

__global__ void __launch_bounds__(256, 1) epilogue_kernel(
    const float* __restrict__ c,
    const float* __restrict__ gi, const float* __restrict__ bi,
    const float* __restrict__ gh, const float* __restrict__ bh,
    const float* __restrict__ gc, const float* __restrict__ bc,
    const float* __restrict__ bias,
    float* __restrict__ out)
{
    __shared__ float si[FH];
    __shared__ float sh[FH];
    __shared__ float red[8];

    const int row = blockIdx.x;
    const int tid = threadIdx.x;
    const float4* pi = (const float4*)(g_scratch + OFF_I2H + (size_t)row * FH);
    const float4* ph = (const float4*)(g_scratch + OFF_H2H + (size_t)row * FH);

    float s1 = 0.f, s2 = 0.f, t1 = 0.f, t2 = 0.f;
    #pragma unroll
    for (int idx = tid; idx < FH / 4; idx += 256) {
        float4 v = pi[idx];
        ((float4*)si)[idx] = v;
        s1 += v.x + v.y + v.z + v.w;
        s2 += v.x * v.x + v.y * v.y + v.z * v.z + v.w * v.w;
        float4 w = ph[idx];
        ((float4*)sh)[idx] = w;
        t1 += w.x + w.y + w.z + w.w;
        t2 += w.x * w.x + w.y * w.y + w.z * w.z + w.w * w.w;
    }
    float S1 = block_reduce(s1, red);
    float S2 = block_reduce(s2, red);
    float T1 = block_reduce(t1, red);
    float T2 = block_reduce(t2, red);

    const float inv = 1.f / (float)FH;
    const float mu_i = S1 * inv, mu_h = T1 * inv;
    const float rs_i = rsqrtf(S2 * inv - mu_i * mu_i + EPS);
    const float rs_h = rsqrtf(T2 * inv - mu_h * mu_h + EPS);

    float cn[4], lo_[4];
    float cs1 = 0.f, cs2 = 0.f;
    #pragma unroll
    for (int kq = 0; kq < 4; kq++) {
        const int j = tid + kq * 256;
        const int jf = j, ji = j + 1024, jo = j + 2048, jg = j + 3072;
        float lf = (si[jf] - mu_i) * rs_i * gi[jf] + bi[jf] + (sh[jf] - mu_h) * rs_h * gh[jf] + bh[jf] + bias[jf];
        float li = (si[ji] - mu_i) * rs_i * gi[ji] + bi[ji] + (sh[ji] - mu_h) * rs_h * gh[ji] + bh[ji] + bias[ji];
        float lo = (si[jo] - mu_i) * rs_i * gi[jo] + bi[jo] + (sh[jo] - mu_h) * rs_h * gh[jo] + bh[jo] + bias[jo];
        float lg = (si[jg] - mu_i) * rs_i * gi[jg] + bi[jg] + (sh[jg] - mu_h) * rs_h * gh[jg] + bh[jg] + bias[jg];
        float cv = sigf(lf) * c[(size_t)row * H_DIM + j] + sigf(li) * tanhf(lg);
        cn[kq] = cv; lo_[kq] = lo;
        cs1 += cv; cs2 += cv * cv;
    }
    float C1 = block_reduce(cs1, red);
    float C2 = block_reduce(cs2, red);
    const float invH = 1.f / (float)H_DIM;
    const float mu_c = C1 * invH;
    const float rs_c = rsqrtf(C2 * invH - mu_c * mu_c + EPS);

    float* out_h = out;
    float* out_c = out + (size_t)B_ROWS * H_DIM;
    #pragma unroll
    for (int kq = 0; kq < 4; kq++) {
        const int j = tid + kq * 256;
        float cl = (cn[kq] - mu_c) * rs_c * gc[j] + bc[j];
        out_h[(size_t)row * H_DIM + j] = sigf(lo_[kq]) * tanhf(cl);
        out_c[(size_t)row * H_DIM + j] = cn[kq];
    }
}

// ===========================================================================
extern "C" void kernel_launch(void* const* d_in, const int* in_sizes, int n_in,
                              void* d_out, int out_size) {
    const float* x    = (const float*)d_in[0];
    const float* h    = (const float*)d_in[1];
    const float* c    = (const float*)d_in[2];
    const float* Wi   = (const float*)d_in[3];
    const float* Wh   = (const float*)d_in[4];
    const float* gi   = (const float*)d_in[5];
    const float* bi   = (const float*)d_in[6];
    const float* gh   = (const float*)d_in[7];
    const float* bh   = (const float*)d_in[8];
    const float* gc   = (const float*)d_in[9];
    const float* bc   = (const float*)d_in[10];
    const float* bias = (const float*)d_in[11];
    float* out = (float*)d_out;

    float* base = nullptr;
    cudaGetSymbolAddress((void**)&base, g_scratch);
    cudaFuncSetAttribute(gemm_tc_kernel, cudaFuncAttributeMaxDynamicSharedMemorySize,
                         STAGES * STAGE_BYTES);
    float* xc  = base + OFF_XC;
    float* hc  = base + OFF_HC;
    float* Wic = base + OFF_WIC;
    float* Whc = base + OFF_WHC;

    // 1) RN-convert operands to tf32
    conv_tf32_kernel<<<4096, 256>>>((const float4*)x,  (uint4*)xc,  (B_ROWS * K_DIM) / 4);
    conv_tf32_kernel<<<4096, 256>>>((const float4*)h,  (uint4*)hc,  (B_ROWS * H_DIM) / 4);
    conv_tf32_kernel<<<2048, 256>>>((const float4*)Wi, (uint4*)Wic, (FH * K_DIM) / 4);
    conv_tf32_kernel<<<2048, 256>>>((const float4*)Wh, (uint4*)Whc, (FH * H_DIM) / 4);

    // 2) tensor-core GEMMs (tf32 mma.sync)
    dim3 gg(FH / 128, B_ROWS / 128, 2);
    gemm_tc_kernel<<<gg, 256, STAGES * STAGE_BYTES>>>(xc, hc, Wic, Whc);

    // 3) fused LN + LSTM epilogue
    epilogue_kernel<<<B_ROWS, 256>>>(c, gi, bi, gh, bh, gc, bc, bias, out);
}

// round 6
// speedup vs baseline: 3.8598x; 1.0554x over previous
#include <cuda_runtime.h>
#include <cstdint>
#include <math.h>

#define B_ROWS 16384
#define K_DIM  1024
#define H_DIM  1024
#define FH     4096
#define EPS    1e-5f

// Scratch: [i2h 64M][h2h 64M][xc 16M][hc 16M][Wic 4M][Whc 4M][stats 64K] floats
#define OFF_I2H   0
#define OFF_H2H   67108864ull
#define OFF_XC    134217728ull
#define OFF_HC    150994944ull
#define OFF_WIC   167772160ull
#define OFF_WHC   171966464ull
#define OFF_STATS 176160768ull
__device__ float g_scratch[176226304];

__device__ __forceinline__ uint32_t smem_u32(const void* p) {
    uint32_t a;
    asm("{ .reg .u64 t; cvta.to.shared.u64 t, %1; cvt.u32.u64 %0, t; }" : "=r"(a) : "l"(p));
    return a;
}

// ===========================================================================
// tf32 RN conversion pass
// ===========================================================================
__global__ void conv_tf32_kernel(const float4* __restrict__ in, uint4* __restrict__ out, int n4) {
    for (int i = blockIdx.x * blockDim.x + threadIdx.x; i < n4; i += gridDim.x * blockDim.x) {
        float4 v = in[i];
        uint4 o;
        asm("cvt.rna.tf32.f32 %0, %1;" : "=r"(o.x) : "f"(v.x));
        asm("cvt.rna.tf32.f32 %0, %1;" : "=r"(o.y) : "f"(v.y));
        asm("cvt.rna.tf32.f32 %0, %1;" : "=r"(o.z) : "f"(v.z));
        asm("cvt.rna.tf32.f32 %0, %1;" : "=r"(o.w) : "f"(v.w));
        out[i] = o;
    }
}

// Zero the per-row LN stats buffer: [2][16384][2] floats = 64K floats
__global__ void zero_stats_kernel() {
    float4* p = (float4*)(g_scratch + OFF_STATS);
    p[blockIdx.x * 256 + threadIdx.x] = make_float4(0.f, 0.f, 0.f, 0.f);
}

// ===========================================================================
// tf32 mma.sync GEMM + fused per-row LN partial stats
// ===========================================================================
#define STAGES 4
#define ITERS  32
#define STAGE_BYTES 32768
#define ROW_BYTES 128

__device__ __forceinline__ void stage_load(uint32_t abase, uint32_t bbase,
                                           const float* __restrict__ A, const float* __restrict__ W,
                                           int m0, int n0, int kb, int tid) {
    #pragma unroll
    for (int i = 0; i < 4; i++) {
        int c = tid + i * 256;
        int r = c >> 3, q = c & 7;
        uint32_t sw = (uint32_t)(r * ROW_BYTES + (((q ^ (r & 7))) << 4));
        const float* ga = A + (size_t)(m0 + r) * K_DIM + kb + q * 4;
        const float* gb = W + (size_t)(n0 + r) * K_DIM + kb + q * 4;
        asm volatile("cp.async.cg.shared.global [%0], [%1], 16;" :: "r"(abase + sw), "l"(ga));
        asm volatile("cp.async.cg.shared.global [%0], [%1], 16;" :: "r"(bbase + sw), "l"(gb));
    }
    asm volatile("cp.async.commit_group;" ::: "memory");
}

#define LDSM_X4(r0, r1, r2, r3, a) \
    asm volatile("ldmatrix.sync.aligned.m8n8.x4.shared.b16 {%0,%1,%2,%3}, [%4];" \
        : "=r"(r0), "=r"(r1), "=r"(r2), "=r"(r3) : "r"(a))

#define MMA_TF32(d, a, b) \
    asm volatile("mma.sync.aligned.m16n8k8.row.col.f32.tf32.tf32.f32 " \
        "{%0,%1,%2,%3}, {%4,%5,%6,%7}, {%8,%9}, {%0,%1,%2,%3};" \
        : "+f"((d)[0]), "+f"((d)[1]), "+f"((d)[2]), "+f"((d)[3]) \
        : "r"((a)[0]), "r"((a)[1]), "r"((a)[2]), "r"((a)[3]), "r"((b)[0]), "r"((b)[1]))

__global__ void __launch_bounds__(256, 1) gemm_tc_kernel(
    const float* __restrict__ A0, const float* __restrict__ A1,
    const float* __restrict__ W0, const float* __restrict__ W1)
{
    extern __shared__ __align__(128) char smem[];
    const uint32_t sb = smem_u32(smem);
    const int tid = threadIdx.x, wid = tid >> 5, l = tid & 31;
    const int m0 = blockIdx.y * 128, n0 = blockIdx.x * 128;
    const int z = blockIdx.z;
    const float* A = z ? A1 : A0;
    const float* W = z ? W1 : W0;
    float* C = g_scratch + (z ? OFF_H2H : OFF_I2H);
    float* stats = g_scratch + OFF_STATS + (size_t)z * B_ROWS * 2;

    const int mw = (wid & 3) * 32;
    const int nw = (wid >> 2) * 64;

    const int rA0 = mw + ((l >> 3) & 1) * 8 + (l & 7);
    const int cbA = (l >> 4);
    const int rB0 = nw + (l >> 4) * 8 + (l & 7);
    const int cbB = (l >> 3) & 1;

    uint32_t offA[2]; int xA[2];
    #pragma unroll
    for (int mf = 0; mf < 2; mf++) { int r = rA0 + mf * 16; offA[mf] = r * ROW_BYTES; xA[mf] = r & 7; }
    uint32_t offB[4]; int xB[4];
    #pragma unroll
    for (int p = 0; p < 4; p++) { int r = rB0 + p * 16; offB[p] = r * ROW_BYTES; xB[p] = r & 7; }

    float acc[2][8][4];
    #pragma unroll
    for (int mf = 0; mf < 2; mf++)
        #pragma unroll
        for (int nf = 0; nf < 8; nf++)
            #pragma unroll
            for (int e = 0; e < 4; e++) acc[mf][nf][e] = 0.f;

    #pragma unroll
    for (int s = 0; s < STAGES - 1; s++)
        stage_load(sb + s * STAGE_BYTES, sb + s * STAGE_BYTES + 16384, A, W, m0, n0, s * 32, tid);

    uint32_t af[2][2][4];
    uint32_t bf[2][4][4];

    for (int kt = 0; kt < ITERS; kt++) {
        asm volatile("cp.async.wait_group 2;" ::: "memory");
        __syncthreads();
        const uint32_t Ab = sb + (kt & (STAGES - 1)) * STAGE_BYTES;
        const uint32_t Bb = Ab + 16384;

        #pragma unroll
        for (int mf = 0; mf < 2; mf++) {
            uint32_t a = Ab + offA[mf] + (((cbA) ^ xA[mf]) << 4);
            LDSM_X4(af[0][mf][0], af[0][mf][1], af[0][mf][2], af[0][mf][3], a);
        }
        #pragma unroll
        for (int p = 0; p < 4; p++) {
            uint32_t a = Bb + offB[p] + (((cbB) ^ xB[p]) << 4);
            LDSM_X4(bf[0][p][0], bf[0][p][1], bf[0][p][2], bf[0][p][3], a);
        }

        if (kt + STAGES - 1 < ITERS) {
            const uint32_t Pb = sb + ((kt + STAGES - 1) & (STAGES - 1)) * STAGE_BYTES;
            stage_load(Pb, Pb + 16384, A, W, m0, n0, (kt + STAGES - 1) * 32, tid);
        } else {
            asm volatile("cp.async.commit_group;" ::: "memory");
        }

        #pragma unroll
        for (int j = 0; j < 4; j++) {
            const int cur = j & 1, nxt = cur ^ 1;
            if (j < 3) {
                const int q = 2 * (j + 1);
                #pragma unroll
                for (int mf = 0; mf < 2; mf++) {
                    uint32_t a = Ab + offA[mf] + (((q + cbA) ^ xA[mf]) << 4);
                    LDSM_X4(af[nxt][mf][0], af[nxt][mf][1], af[nxt][mf][2], af[nxt][mf][3], a);
                }
                #pragma unroll
                for (int p = 0; p < 4; p++) {
                    uint32_t a = Bb + offB[p] + (((q + cbB) ^ xB[p]) << 4);
                    LDSM_X4(bf[nxt][p][0], bf[nxt][p][1], bf[nxt][p][2], bf[nxt][p][3], a);
                }
            }
            #pragma unroll
            for (int mf = 0; mf < 2; mf++)
                #pragma unroll
                for (int nf = 0; nf < 8; nf++) {
                    uint32_t b2[2] = { bf[cur][nf >> 1][(nf & 1) * 2], bf[cur][nf >> 1][(nf & 1) * 2 + 1] };
                    MMA_TF32(acc[mf][nf], af[cur][mf], b2);
                }
        }
    }

    // ---- store C + fused per-row LN partial stats ----
    const int g = l >> 2, cc = (l & 3) * 2;
    #pragma unroll
    for (int mf = 0; mf < 2; mf++) {
        float s0 = 0.f, q0 = 0.f, s1 = 0.f, q1 = 0.f;
        #pragma unroll
        for (int nf = 0; nf < 8; nf++) {
            const int col = n0 + nw + nf * 8 + cc;
            float* p0 = C + (size_t)(m0 + mw + mf * 16 + g) * FH + col;
            float* p1 = p0 + 8 * FH;
            asm volatile("st.global.v2.f32 [%0], {%1,%2};" :: "l"(p0), "f"(acc[mf][nf][0]), "f"(acc[mf][nf][1]) : "memory");
            asm volatile("st.global.v2.f32 [%0], {%1,%2};" :: "l"(p1), "f"(acc[mf][nf][2]), "f"(acc[mf][nf][3]) : "memory");
            s0 += acc[mf][nf][0] + acc[mf][nf][1];
            q0 += acc[mf][nf][0] * acc[mf][nf][0] + acc[mf][nf][1] * acc[mf][nf][1];
            s1 += acc[mf][nf][2] + acc[mf][nf][3];
            q1 += acc[mf][nf][2] * acc[mf][nf][2] + acc[mf][nf][3] * acc[mf][nf][3];
        }
        // reduce across the 4 lanes sharing a row (l&3)
        #pragma unroll
        for (int o = 1; o < 4; o <<= 1) {
            s0 += __shfl_xor_sync(0xffffffffu, s0, o);
            q0 += __shfl_xor_sync(0xffffffffu, q0, o);
            s1 += __shfl_xor_sync(0xffffffffu, s1, o);
            q1 += __shfl_xor_sync(0xffffffffu, q1, o);
        }
        if ((l & 3) == 0) {
            const int r0 = m0 + mw + mf * 16 + g;
            atomicAdd(&stats[(size_t)r0 * 2 + 0], s0);
            atomicAdd(&stats[(size_t)r0 * 2 + 1], q0);
            atomicAdd(&stats[(size_t)(r0 + 8) * 2 + 0], s1);
            atomicAdd(&stats[(size_t)(r0 + 8) * 2 + 1], q1);
        }
    }
}

// ===========================================================================
// Streaming one-pass LN+LSTM epilogue (LN stats precomputed by GEMM)
// ===========================================================================
__device__ __forceinline__ float sigf(float x) { return 1.f / (1.f + expf(-x)); }

__global__ void __launch_bounds__(256, 4) epilogue_kernel(
    const float* __restrict__ c,
    const float* __restrict__ gi, const float* __restrict__ bi,
    const float* __restrict__ gh, const float* __restrict__ bh,
    const float* __restrict__ gc, const float* __restrict__ bc,
    const float* __restrict__ bias,
    float* __restrict__ out)
{
    __shared__ float red[16];
    const int row = blockIdx.x;
    const int t = threadIdx.x;

    const float2* sti_p = (const float2*)(g_scratch + OFF_STATS);
    const float2 sti = sti_p[row];
    const float2 sth = sti_p[B_ROWS + row];
    const float inv = 1.f / (float)FH;
    const float mu_i = sti.x * inv;
    const float mu_h = sth.x * inv;
    const float rs_i = rsqrtf(sti.y * inv - mu_i * mu_i + EPS);
    const float rs_h = rsqrtf(sth.y * inv - mu_h * mu_h + EPS);

    const float* i2h = g_scratch + OFF_I2H + (size_t)row * FH;
    const float* h2h = g_scratch + OFF_H2H + (size_t)row * FH;

    float4 lg4[4];   // logits per gate (f, i, o, g), 4 consecutive cols at 4t
    #pragma unroll
    for (int gate = 0; gate < 4; gate++) {
        const int jo = gate * 1024 + 4 * t;
        const float4 vi = *(const float4*)(i2h + jo);
        const float4 vh = *(const float4*)(h2h + jo);
        const float4 ga = *(const float4*)(gi + jo);
        const float4 ba = *(const float4*)(bi + jo);
        const float4 gb = *(const float4*)(gh + jo);
        const float4 bb = *(const float4*)(bh + jo);
        const float4 bs = *(const float4*)(bias + jo);
        float4 r;
        r.x = (vi.x - mu_i) * rs_i * ga.x + ba.x + (vh.x - mu_h) * rs_h * gb.x + bb.x + bs.x;
        r.y = (vi.y - mu_i) * rs_i * ga.y + ba.y + (vh.y - mu_h) * rs_h * gb.y + bb.y + bs.y;
        r.z = (vi.z - mu_i) * rs_i * ga.z + ba.z + (vh.z - mu_h) * rs_h * gb.z + bb.z + bs.z;
        r.w = (vi.w - mu_i) * rs_i * ga.w + ba.w + (vh.w - mu_h) * rs_h * gb.w + bb.w + bs.w;
        lg4[gate] = r;
    }

    const float4 cv_old = *(const float4*)(c + (size_t)row * H_DIM + 4 * t);
    float4 cn;
    cn.x = sigf(lg4[0].x) * cv_old.x + sigf(lg4[1].x) * tanhf(lg4[3].x);
    cn.y = sigf(lg4[0].y) * cv_old.y + sigf(lg4[1].y) * tanhf(lg4[3].y);
    cn.z = sigf(lg4[0].z) * cv_old.z + sigf(lg4[1].z) * tanhf(lg4[3].z);
    cn.w = sigf(lg4[0].w) * cv_old.w + sigf(lg4[1].w) * tanhf(lg4[3].w);

    // block reduce c_new stats (sum, sumsq)
    float cs1 = cn.x + cn.y + cn.z + cn.w;
    float cs2 = cn.x * cn.x + cn.y * cn.y + cn.z * cn.z + cn.w * cn.w;
    #pragma unroll
    for (int o = 16; o > 0; o >>= 1) {
        cs1 += __shfl_xor_sync(0xffffffffu, cs1, o);
        cs2 += __shfl_xor_sync(0xffffffffu, cs2, o);
    }
    if ((t & 31) == 0) { red[t >> 5] = cs1; red[8 + (t >> 5)] = cs2; }
    __syncthreads();
    float C1 = red[0], C2 = red[8];
    #pragma unroll
    for (int w = 1; w < 8; w++) { C1 += red[w]; C2 += red[8 + w]; }

    const float invH = 1.f / (float)H_DIM;
    const float mu_c = C1 * invH;
    const float rs_c = rsqrtf(C2 * invH - mu_c * mu_c + EPS);

    const float4 gcv = *(const float4*)(gc + 4 * t);
    const float4 bcv = *(const float4*)(bc + 4 * t);
    float4 hv;
    hv.x = sigf(lg4[2].x) * tanhf((cn.x - mu_c) * rs_c * gcv.x + bcv.x);
    hv.y = sigf(lg4[2].y) * tanhf((cn.y - mu_c) * rs_c * gcv.y + bcv.y);
    hv.z = sigf(lg4[2].z) * tanhf((cn.z - mu_c) * rs_c * gcv.z + bcv.z);
    hv.w = sigf(lg4[2].w) * tanhf((cn.w - mu_c) * rs_c * gcv.w + bcv.w);

    *(float4*)(out + (size_t)row * H_DIM + 4 * t) = hv;
    *(float4*)(out + (size_t)B_ROWS * H_DIM + (size_t)row * H_DIM + 4 * t) = cn;
}

// ===========================================================================
extern "C" void kernel_launch(void* const* d_in, const int* in_sizes, int n_in,
                              void* d_out, int out_size) {
    const float* x    = (const float*)d_in[0];
    const float* h    = (const float*)d_in[1];
    const float* c    = (const float*)d_in[2];
    const float* Wi   = (const float*)d_in[3];
    const float* Wh   = (const float*)d_in[4];
    const float* gi   = (const float*)d_in[5];
    const float* bi   = (const float*)d_in[6];
    const float* gh   = (const float*)d_in[7];
    const float* bh   = (const float*)d_in[8];
    const float* gc   = (const float*)d_in[9];
    const float* bc   = (const float*)d_in[10];
    const float* bias = (const float*)d_in[11];
    float* out = (float*)d_out;

    float* base = nullptr;
    cudaGetSymbolAddress((void**)&base, g_scratch);
    cudaFuncSetAttribute(gemm_tc_kernel, cudaFuncAttributeMaxDynamicSharedMemorySize,
                         STAGES * STAGE_BYTES);
    float* xc  = base + OFF_XC;
    float* hc  = base + OFF_HC;
    float* Wic = base + OFF_WIC;
    float* Whc = base + OFF_WHC;

    // 1) RN-convert operands to tf32
    conv_tf32_kernel<<<4096, 256>>>((const float4*)x,  (uint4*)xc,  (B_ROWS * K_DIM) / 4);
    conv_tf32_kernel<<<4096, 256>>>((const float4*)h,  (uint4*)hc,  (B_ROWS * H_DIM) / 4);
    conv_tf32_kernel<<<2048, 256>>>((const float4*)Wi, (uint4*)Wic, (FH * K_DIM) / 4);
    conv_tf32_kernel<<<2048, 256>>>((const float4*)Wh, (uint4*)Whc, (FH * H_DIM) / 4);

    // 2) zero LN stats
    zero_stats_kernel<<<64, 256>>>();

    // 3) tensor-core GEMMs + fused LN stats
    dim3 gg(FH / 128, B_ROWS / 128, 2);
    gemm_tc_kernel<<<gg, 256, STAGES * STAGE_BYTES>>>(xc, hc, Wic, Whc);

    // 4) streaming LN + LSTM epilogue
    epilogue_kernel<<<B_ROWS, 256>>>(c, gi, bi, gh, bh, gc, bc, bias, out);
}

// round 8
// speedup vs baseline: 4.1781x; 1.0825x over previous
#include <cuda_runtime.h>
#include <cstdint>
#include <math.h>

#define B_ROWS 16384
#define K_DIM  1024
#define H_DIM  1024
#define FH     4096
#define EPS    1e-5f

// Scratch: [i2h 64M][h2h 64M][xc 16M][hc 16M][Wic 4M][Whc 4M][stats 64K] floats
#define OFF_I2H   0
#define OFF_H2H   67108864ull
#define OFF_XC    134217728ull
#define OFF_HC    150994944ull
#define OFF_WIC   167772160ull
#define OFF_WHC   171966464ull
#define OFF_STATS 176160768ull
__device__ float g_scratch[176226304];

__device__ __forceinline__ uint32_t smem_u32(const void* p) {
    uint32_t a;
    asm("{ .reg .u64 t; cvta.to.shared.u64 t, %1; cvt.u32.u64 %0, t; }" : "=r"(a) : "l"(p));
    return a;
}

// ===========================================================================
// tf32 RN conversion pass
// ===========================================================================
__global__ void conv_tf32_kernel(const float4* __restrict__ in, uint4* __restrict__ out, int n4) {
    for (int i = blockIdx.x * blockDim.x + threadIdx.x; i < n4; i += gridDim.x * blockDim.x) {
        float4 v = in[i];
        uint4 o;
        asm("cvt.rna.tf32.f32 %0, %1;" : "=r"(o.x) : "f"(v.x));
        asm("cvt.rna.tf32.f32 %0, %1;" : "=r"(o.y) : "f"(v.y));
        asm("cvt.rna.tf32.f32 %0, %1;" : "=r"(o.z) : "f"(v.z));
        asm("cvt.rna.tf32.f32 %0, %1;" : "=r"(o.w) : "f"(v.w));
        out[i] = o;
    }
}

// Zero the per-row LN stats buffer
__global__ void zero_stats_kernel() {
    float4* p = (float4*)(g_scratch + OFF_STATS);
    p[blockIdx.x * 256 + threadIdx.x] = make_float4(0.f, 0.f, 0.f, 0.f);
}

// ===========================================================================
// tf32 mma.sync GEMM, tile 128(M) x 256(N) x 32(K), 256 threads,
// 8 warps (2m x 4n), warp tile 64x64, 4-stage cp.async ring, fused LN stats.
// ===========================================================================
#define STAGES 4
#define ITERS  32
#define STAGE_BYTES 49152     // A 16KB + B 32KB
#define ROW_BYTES 128

__device__ __forceinline__ void stage_load(uint32_t abase, uint32_t bbase,
                                           const float* __restrict__ A, const float* __restrict__ W,
                                           int m0, int n0, int kb, int tid) {
    // A: 1024 16B chunks (128 rows x 8), B: 2048 chunks (256 rows x 8)
    #pragma unroll
    for (int i = 0; i < 4; i++) {
        int c = tid + i * 256;
        int r = c >> 3, q = c & 7;
        uint32_t sw = (uint32_t)(r * ROW_BYTES + ((q ^ (r & 7)) << 4));
        const float* ga = A + (size_t)(m0 + r) * K_DIM + kb + q * 4;
        asm volatile("cp.async.cg.shared.global [%0], [%1], 16;" :: "r"(abase + sw), "l"(ga));
    }
    #pragma unroll
    for (int i = 0; i < 8; i++) {
        int c = tid + i * 256;
        int r = c >> 3, q = c & 7;
        uint32_t sw = (uint32_t)(r * ROW_BYTES + ((q ^ (r & 7)) << 4));
        const float* gb = W + (size_t)(n0 + r) * K_DIM + kb + q * 4;
        asm volatile("cp.async.cg.shared.global [%0], [%1], 16;" :: "r"(bbase + sw), "l"(gb));
    }
    asm volatile("cp.async.commit_group;" ::: "memory");
}

#define LDSM_X4(r0, r1, r2, r3, a) \
    asm volatile("ldmatrix.sync.aligned.m8n8.x4.shared.b16 {%0,%1,%2,%3}, [%4];" \
        : "=r"(r0), "=r"(r1), "=r"(r2), "=r"(r3) : "r"(a))

#define MMA_TF32(d, a, b) \
    asm volatile("mma.sync.aligned.m16n8k8.row.col.f32.tf32.tf32.f32 " \
        "{%0,%1,%2,%3}, {%4,%5,%6,%7}, {%8,%9}, {%0,%1,%2,%3};" \
        : "+f"((d)[0]), "+f"((d)[1]), "+f"((d)[2]), "+f"((d)[3]) \
        : "r"((a)[0]), "r"((a)[1]), "r"((a)[2]), "r"((a)[3]), "r"((b)[0]), "r"((b)[1]))

__global__ void __launch_bounds__(256, 1) gemm_tc_kernel(
    const float* __restrict__ A0, const float* __restrict__ A1,
    const float* __restrict__ W0, const float* __restrict__ W1)
{
    extern __shared__ __align__(128) char smem[];
    const uint32_t sb = smem_u32(smem);
    const int tid = threadIdx.x, wid = tid >> 5, l = tid & 31;
    const int m0 = blockIdx.y * 128, n0 = blockIdx.x * 256;
    const int z = blockIdx.z;
    const float* A = z ? A1 : A0;
    const float* W = z ? W1 : W0;
    float* C = g_scratch + (z ? OFF_H2H : OFF_I2H);
    float* stats = g_scratch + OFF_STATS + (size_t)z * B_ROWS * 2;

    const int mw = (wid & 1) * 64;       // warp m offset (2 warps in m)
    const int nw = (wid >> 1) * 64;      // warp n offset (4 warps in n)

    const int rA0 = mw + ((l >> 3) & 1) * 8 + (l & 7);
    const int cbA = (l >> 4);
    const int rB0 = nw + (l >> 4) * 8 + (l & 7);
    const int cbB = (l >> 3) & 1;

    uint32_t offA[4]; int xA[4];
    #pragma unroll
    for (int mf = 0; mf < 4; mf++) { int r = rA0 + mf * 16; offA[mf] = r * ROW_BYTES; xA[mf] = r & 7; }
    uint32_t offB[4]; int xB[4];
    #pragma unroll
    for (int p = 0; p < 4; p++) { int r = rB0 + p * 16; offB[p] = r * ROW_BYTES; xB[p] = r & 7; }

    float acc[4][8][4];
    #pragma unroll
    for (int mf = 0; mf < 4; mf++)
        #pragma unroll
        for (int nf = 0; nf < 8; nf++)
            #pragma unroll
            for (int e = 0; e < 4; e++) acc[mf][nf][e] = 0.f;

    #pragma unroll
    for (int s = 0; s < STAGES - 1; s++)
        stage_load(sb + s * STAGE_BYTES, sb + s * STAGE_BYTES + 16384, A, W, m0, n0, s * 32, tid);

    uint32_t af[2][4][4];
    uint32_t bf[2][4][4];

    for (int kt = 0; kt < ITERS; kt++) {
        asm volatile("cp.async.wait_group 2;" ::: "memory");
        __syncthreads();
        const uint32_t Ab = sb + (kt & (STAGES - 1)) * STAGE_BYTES;
        const uint32_t Bb = Ab + 16384;

        #pragma unroll
        for (int mf = 0; mf < 4; mf++) {
            uint32_t a = Ab + offA[mf] + ((cbA ^ xA[mf]) << 4);
            LDSM_X4(af[0][mf][0], af[0][mf][1], af[0][mf][2], af[0][mf][3], a);
        }
        #pragma unroll
        for (int p = 0; p < 4; p++) {
            uint32_t a = Bb + offB[p] + ((cbB ^ xB[p]) << 4);
            LDSM_X4(bf[0][p][0], bf[0][p][1], bf[0][p][2], bf[0][p][3], a);
        }

        if (kt + STAGES - 1 < ITERS) {
            const uint32_t Pb = sb + ((kt + STAGES - 1) & (STAGES - 1)) * STAGE_BYTES;
            stage_load(Pb, Pb + 16384, A, W, m0, n0, (kt + STAGES - 1) * 32, tid);
        } else {
            asm volatile("cp.async.commit_group;" ::: "memory");
        }

        #pragma unroll
        for (int j = 0; j < 4; j++) {
            const int cur = j & 1, nxt = cur ^ 1;
            if (j < 3) {
                const int q = 2 * (j + 1);
                #pragma unroll
                for (int mf = 0; mf < 4; mf++) {
                    uint32_t a = Ab + offA[mf] + (((q + cbA) ^ xA[mf]) << 4);
                    LDSM_X4(af[nxt][mf][0], af[nxt][mf][1], af[nxt][mf][2], af[nxt][mf][3], a);
                }
                #pragma unroll
                for (int p = 0; p < 4; p++) {
                    uint32_t a = Bb + offB[p] + (((q + cbB) ^ xB[p]) << 4);
                    LDSM_X4(bf[nxt][p][0], bf[nxt][p][1], bf[nxt][p][2], bf[nxt][p][3], a);
                }
            }
            #pragma unroll
            for (int mf = 0; mf < 4; mf++)
                #pragma unroll
                for (int nf = 0; nf < 8; nf++) {
                    uint32_t b2[2] = { bf[cur][nf >> 1][(nf & 1) * 2], bf[cur][nf >> 1][(nf & 1) * 2 + 1] };
                    MMA_TF32(acc[mf][nf], af[cur][mf], b2);
                }
        }
    }

    // ---- store C + fused per-row LN partial stats ----
    const int g = l >> 2, cc = (l & 3) * 2;
    #pragma unroll
    for (int mf = 0; mf < 4; mf++) {
        float s0 = 0.f, q0 = 0.f, s1 = 0.f, q1 = 0.f;
        #pragma unroll
        for (int nf = 0; nf < 8; nf++) {
            const int col = n0 + nw + nf * 8 + cc;
            float* p0 = C + (size_t)(m0 + mw + mf * 16 + g) * FH + col;
            float* p1 = p0 + 8 * FH;
            asm volatile("st.global.v2.f32 [%0], {%1,%2};" :: "l"(p0), "f"(acc[mf][nf][0]), "f"(acc[mf][nf][1]) : "memory");
            asm volatile("st.global.v2.f32 [%0], {%1,%2};" :: "l"(p1), "f"(acc[mf][nf][2]), "f"(acc[mf][nf][3]) : "memory");
            s0 += acc[mf][nf][0] + acc[mf][nf][1];
            q0 += acc[mf][nf][0] * acc[mf][nf][0] + acc[mf][nf][1] * acc[mf][nf][1];
            s1 += acc[mf][nf][2] + acc[mf][nf][3];
            q1 += acc[mf][nf][2] * acc[mf][nf][2] + acc[mf][nf][3] * acc[mf][nf][3];
        }
        #pragma unroll
        for (int o = 1; o < 4; o <<= 1) {
            s0 += __shfl_xor_sync(0xffffffffu, s0, o);
            q0 += __shfl_xor_sync(0xffffffffu, q0, o);
            s1 += __shfl_xor_sync(0xffffffffu, s1, o);
            q1 += __shfl_xor_sync(0xffffffffu, q1, o);
        }
        if ((l & 3) == 0) {
            const int r0 = m0 + mw + mf * 16 + g;
            atomicAdd(&stats[(size_t)r0 * 2 + 0], s0);
            atomicAdd(&stats[(size_t)r0 * 2 + 1], q0);
            atomicAdd(&stats[(size_t)(r0 + 8) * 2 + 0], s1);
            atomicAdd(&stats[(size_t)(r0 + 8) * 2 + 1], q1);
        }
    }
}

// ===========================================================================
// Streaming one-pass LN+LSTM epilogue (LN stats precomputed by GEMM)
// ===========================================================================
__device__ __forceinline__ float sigf(float x) { return 1.f / (1.f + expf(-x)); }

__global__ void __launch_bounds__(256, 4) epilogue_kernel(
    const float* __restrict__ c,
    const float* __restrict__ gi, const float* __restrict__ bi,
    const float* __restrict__ gh, const float* __restrict__ bh,
    const float* __restrict__ gc, const float* __restrict__ bc,
    const float* __restrict__ bias,
    float* __restrict__ out)
{
    __shared__ float red[16];
    const int row = blockIdx.x;
    const int t = threadIdx.x;

    const float2* sti_p = (const float2*)(g_scratch + OFF_STATS);
    const float2 sti = sti_p[row];
    const float2 sth = sti_p[B_ROWS + row];
    const float inv = 1.f / (float)FH;
    const float mu_i = sti.x * inv;
    const float mu_h = sth.x * inv;
    const float rs_i = rsqrtf(sti.y * inv - mu_i * mu_i + EPS);
    const float rs_h = rsqrtf(sth.y * inv - mu_h * mu_h + EPS);

    const float* i2h = g_scratch + OFF_I2H + (size_t)row * FH;
    const float* h2h = g_scratch + OFF_H2H + (size_t)row * FH;

    float4 lg4[4];
    #pragma unroll
    for (int gate = 0; gate < 4; gate++) {
        const int jo = gate * 1024 + 4 * t;
        const float4 vi = *(const float4*)(i2h + jo);
        const float4 vh = *(const float4*)(h2h + jo);
        const float4 ga = *(const float4*)(gi + jo);
        const float4 ba = *(const float4*)(bi + jo);
        const float4 gb = *(const float4*)(gh + jo);
        const float4 bb = *(const float4*)(bh + jo);
        const float4 bs = *(const float4*)(bias + jo);
        float4 r;
        r.x = (vi.x - mu_i) * rs_i * ga.x + ba.x + (vh.x - mu_h) * rs_h * gb.x + bb.x + bs.x;
        r.y = (vi.y - mu_i) * rs_i * ga.y + ba.y + (vh.y - mu_h) * rs_h * gb.y + bb.y + bs.y;
        r.z = (vi.z - mu_i) * rs_i * ga.z + ba.z + (vh.z - mu_h) * rs_h * gb.z + bb.z + bs.z;
        r.w = (vi.w - mu_i) * rs_i * ga.w + ba.w + (vh.w - mu_h) * rs_h * gb.w + bb.w + bs.w;
        lg4[gate] = r;
    }

    const float4 cv_old = *(const float4*)(c + (size_t)row * H_DIM + 4 * t);
    float4 cn;
    cn.x = sigf(lg4[0].x) * cv_old.x + sigf(lg4[1].x) * tanhf(lg4[3].x);
    cn.y = sigf(lg4[0].y) * cv_old.y + sigf(lg4[1].y) * tanhf(lg4[3].y);
    cn.z = sigf(lg4[0].z) * cv_old.z + sigf(lg4[1].z) * tanhf(lg4[3].z);
    cn.w = sigf(lg4[0].w) * cv_old.w + sigf(lg4[1].w) * tanhf(lg4[3].w);

    float cs1 = cn.x + cn.y + cn.z + cn.w;
    float cs2 = cn.x * cn.x + cn.y * cn.y + cn.z * cn.z + cn.w * cn.w;
    #pragma unroll
    for (int o = 16; o > 0; o >>= 1) {
        cs1 += __shfl_xor_sync(0xffffffffu, cs1, o);
        cs2 += __shfl_xor_sync(0xffffffffu, cs2, o);
    }
    if ((t & 31) == 0) { red[t >> 5] = cs1; red[8 + (t >> 5)] = cs2; }
    __syncthreads();
    float C1 = red[0], C2 = red[8];
    #pragma unroll
    for (int w = 1; w < 8; w++) { C1 += red[w]; C2 += red[8 + w]; }

    const float invH = 1.f / (float)H_DIM;
    const float mu_c = C1 * invH;
    const float rs_c = rsqrtf(C2 * invH - mu_c * mu_c + EPS);

    const float4 gcv = *(const float4*)(gc + 4 * t);
    const float4 bcv = *(const float4*)(bc + 4 * t);
    float4 hv;
    hv.x = sigf(lg4[2].x) * tanhf((cn.x - mu_c) * rs_c * gcv.x + bcv.x);
    hv.y = sigf(lg4[2].y) * tanhf((cn.y - mu_c) * rs_c * gcv.y + bcv.y);
    hv.z = sigf(lg4[2].z) * tanhf((cn.z - mu_c) * rs_c * gcv.z + bcv.z);
    hv.w = sigf(lg4[2].w) * tanhf((cn.w - mu_c) * rs_c * gcv.w + bcv.w);

    *(float4*)(out + (size_t)row * H_DIM + 4 * t) = hv;
    *(float4*)(out + (size_t)B_ROWS * H_DIM + (size_t)row * H_DIM + 4 * t) = cn;
}

// ===========================================================================
extern "C" void kernel_launch(void* const* d_in, const int* in_sizes, int n_in,
                              void* d_out, int out_size) {
    const float* x    = (const float*)d_in[0];
    const float* h    = (const float*)d_in[1];
    const float* c    = (const float*)d_in[2];
    const float* Wi   = (const float*)d_in[3];
    const float* Wh   = (const float*)d_in[4];
    const float* gi   = (const float*)d_in[5];
    const float* bi   = (const float*)d_in[6];
    const float* gh   = (const float*)d_in[7];
    const float* bh   = (const float*)d_in[8];
    const float* gc   = (const float*)d_in[9];
    const float* bc   = (const float*)d_in[10];
    const float* bias = (const float*)d_in[11];
    float* out = (float*)d_out;

    float* base = nullptr;
    cudaGetSymbolAddress((void**)&base, g_scratch);
    cudaFuncSetAttribute(gemm_tc_kernel, cudaFuncAttributeMaxDynamicSharedMemorySize,
                         STAGES * STAGE_BYTES);
    float* xc  = base + OFF_XC;
    float* hc  = base + OFF_HC;
    float* Wic = base + OFF_WIC;
    float* Whc = base + OFF_WHC;

    // 1) RN-convert operands to tf32
    conv_tf32_kernel<<<4096, 256>>>((const float4*)x,  (uint4*)xc,  (B_ROWS * K_DIM) / 4);
    conv_tf32_kernel<<<4096, 256>>>((const float4*)h,  (uint4*)hc,  (B_ROWS * H_DIM) / 4);
    conv_tf32_kernel<<<2048, 256>>>((const float4*)Wi, (uint4*)Wic, (FH * K_DIM) / 4);
    conv_tf32_kernel<<<2048, 256>>>((const float4*)Wh, (uint4*)Whc, (FH * H_DIM) / 4);

    // 2) zero LN stats
    zero_stats_kernel<<<64, 256>>>();

    // 3) tensor-core GEMMs + fused LN stats (tile 128x256)
    dim3 gg(FH / 256, B_ROWS / 128, 2);
    gemm_tc_kernel<<<gg, 256, STAGES * STAGE_BYTES>>>(xc, hc, Wic, Whc);

    // 4) streaming LN + LSTM epilogue
    epilogue_kernel<<<B_ROWS, 256>>>(c, gi, bi, gh, bh, gc, bc, bias, out);
}